// round 9
// baseline (speedup 1.0000x reference)
#include <cuda_runtime.h>
#include <math.h>
#include <float.h>

#define NSAMP  160000
#define NF     998
#define FRAME  400
#define HOP    160
#define MAXB   128
#define NLAG   288      // lags 32..319
#define HLAG   152      // hnr lag slots (150 used: lags 50..199)
#define HCHUNK 40
#define HCLEN  4000

typedef unsigned long long u64;

// float-padded smem (scalar path): insert one float after every 8
#define PIDX(i) ((i) + ((i) >> 3))
// pair-padded smem (f32x2 path): u64 slot for pair p (gap every 8 pairs)
#define QSLOT(p) ((p) + ((p) >> 3))
// float index into pair-padded layout
#define VSLOT(i) (2*QSLOT((i) >> 1) + ((i) & 1))

__device__ __forceinline__ u64 f2fma(u64 a, u64 b, u64 c) {
    u64 d; asm("fma.rn.f32x2 %0,%1,%2,%3;" : "=l"(d) : "l"(a), "l"(b), "l"(c)); return d;
}
__device__ __forceinline__ u64 f2pack(float lo, float hi) {
    u64 r; asm("mov.b64 %0,{%1,%2};" : "=l"(r) : "f"(lo), "f"(hi)); return r;
}
__device__ __forceinline__ float f2lo(u64 v) { return __uint_as_float((unsigned)v); }
__device__ __forceinline__ float f2hi(u64 v) { return __uint_as_float((unsigned)(v >> 32)); }

// ------------------------- device scratch (static, no allocs) ---------------
__device__ float g_rms[MAXB*NF];
__device__ float g_zcr[MAXB*NF];
__device__ float g_amp[MAXB*NF];
__device__ float g_f0 [MAXB*NF];
__device__ float g_val[MAXB*NF];
__device__ int   g_pos[MAXB][NSAMP];
__device__ float g_sig[MAXB][12];
__device__ float g_hnrp[(size_t)MAXB*HCHUNK*HLAG];

// ---- k_frames entry tables (18 groups of 16 lags, 261 16-sample tiles) -----
__constant__ int cG [32] = {0,0,0,1,1,2,2,3,3,4,4,5,5,6,6,7,7,8,8,9,9,10,10,11,11,12,12,13,14,15,16,17};
__constant__ int cTA[32] = {0,8,16,0,11,0,11,0,10,0,10,0,9,0,9,0,8,0,8,0,7,0,7,0,6,0,6,0,0,0,0,0};
__constant__ int cTB[32] = {8,16,23,11,22,11,21,10,20,10,19,9,18,9,17,8,16,8,15,7,14,7,13,6,12,6,11,10,9,8,7,6};
// half-B lane->entry map: groups stay lane-contiguous, per-lane A+B tiles <= 17
__constant__ int cPermB[32] = {0,1,2,25,26,23,24,21,22,19,20,17,18,15,16,13,14,11,12,9,10,7,8,5,6,3,4,31,30,29,28,27};
// group-lead lane -> member count (same for both halves); 0 = not a lead
__constant__ int cLeadCnt[32] = {3,0,0,2,0,2,0,2,0,2,0,2,0,2,0,2,0,2,0,2,0,2,0,2,0,2,0,1,1,1,1,1};

// 16-lag sliding-window autocorr, packed f32x2, dual smem copies.
// sA = aligned pairs of s; sB = pairs of s shifted by one (sB[i] = s[i+1]).
// t0, L0, t1 multiples of 16; t1 + L0 <= 400; buffers zero beyond data.
// out[j] = sum_t s[t]*s[t+L0+j], j = 0..15.
__device__ __forceinline__ void ac16v2(const u64* __restrict__ sA,
                                       const u64* __restrict__ sB,
                                       int t0, int L0, int t1, float* out)
{
    u64 wA[8], wB[8], acc[8];
    {
        int s0 = QSLOT((t0 + L0) >> 1);       // (t0+L0)/2 multiple of 8
#pragma unroll
        for (int k = 0; k < 8; k++) {
            wA[k] = sA[s0 + k];
            wB[k] = sB[s0 + k];
            acc[k] = 0ull;
        }
    }
    #pragma unroll 1
    for (int tb = t0; tb < t1; tb += 16) {
        int sb_ = QSLOT(tb >> 1);                  // bb slot base
        int sw_ = QSLOT((tb + L0) >> 1) + 9;       // refill slot base (pairs +8)
#pragma unroll
        for (int u = 0; u < 8; u++) {
            u64 bp = sA[sb_ + u];                  // {s[t], s[t+1]}, t = tb+2u
            float blo = f2lo(bp), bhi = f2hi(bp);
            u64 bbE = f2pack(blo, blo);
            u64 bbO = f2pack(bhi, bhi);
#pragma unroll
            for (int j = 0; j < 8; j++) acc[j] = f2fma(bbE, wA[(u + j) & 7], acc[j]);
#pragma unroll
            for (int j = 0; j < 8; j++) acc[j] = f2fma(bbO, wB[(u + j) & 7], acc[j]);
            wA[u] = sA[sw_ + u];
            wB[u] = sB[sw_ + u];
        }
    }
#pragma unroll
    for (int j = 0; j < 8; j++) { out[2*j] = f2lo(acc[j]); out[2*j+1] = f2hi(acc[j]); }
}

// 16-lag scalar sliding-window autocorr (used by k_hnr; proven).
__device__ __forceinline__ void ac16s(const float* __restrict__ sf,
                                      int t0, int L0, int t1, float* out)
{
    float wreg[16], acc[16];
    int pb0 = PIDX(t0 + L0);
#pragma unroll
    for (int j = 0; j < 16; j++) { wreg[j] = sf[pb0 + j + (j>>3)]; acc[j] = 0.f; }
    #pragma unroll 1
    for (int tb = t0; tb < t1; tb += 16) {
        int pB = PIDX(tb);
        int pW = PIDX(tb + L0 + 16);
#pragma unroll
        for (int u = 0; u < 16; u++) {
            float bb = sf[pB + u + (u>>3)];
#pragma unroll
            for (int j = 0; j < 16; j++) acc[j] += bb * wreg[(u + j) & 15];
            wreg[u] = sf[pW + u + (u>>3)];
        }
    }
#pragma unroll
    for (int j = 0; j < 16; j++) out[j] = acc[j];
}

// ------------------------- K1: per-frame stats + autocorr -------------------
// One warp per frame, 2 frames per warp (buffer reused across halves).
__global__ __launch_bounds__(256) void k_frames(const float* __restrict__ audio)
{
    __shared__ u64 sbuf[8][2][248];   // per-warp {sA, sB}, pair-padded
    const int tid = threadIdx.x, w = tid >> 5, lane = tid & 31;
    const int b = blockIdx.y;
    const int fbase = blockIdx.x*16 + 2*w;
    u64* sA = sbuf[w][0];
    u64* sB = sbuf[w][1];
    float* fA = (float*)sA;
    float* fB = (float*)sB;

    #pragma unroll 1
    for (int half = 0; half < 2; half++) {
        int f = fbase + half;
        if (f >= NF) break;           // warp-uniform
        const float* a = audio + (size_t)b*NSAMP + (size_t)f*HOP;

        // load both copies + stats (rms/zcr/amp fused; sign via shuffles)
        float ss = 0.f, am = 0.f, zc = 0.f, prevs31 = 0.f;
        #pragma unroll 1
        for (int k = 0; k < 14; k++) {
            int i = lane + 32*k;
            float x = (i < FRAME) ? a[i] : 0.f;
            if (i < 440) fA[VSLOT(i)] = x;
            if (i >= 1 && i < 441) fB[VSLOT(i-1)] = x;
            if (i == 0) fB[VSLOT(440)] = 0.f;  // harmless filler
            ss += x*x;
            am = fmaxf(am, fabsf(x));
            float sg = (float)((x > 0.f) - (x < 0.f));
            float ps = __shfl_up_sync(0xffffffffu, sg, 1);
            if (lane == 0) ps = prevs31;
            if (i >= 1 && i < FRAME) zc += fabsf(sg - ps);
            prevs31 = __shfl_sync(0xffffffffu, sg, 31);
        }
        for (int o = 16; o; o >>= 1) {
            ss += __shfl_xor_sync(0xffffffffu, ss, o);
            zc += __shfl_xor_sync(0xffffffffu, zc, o);
            am  = fmaxf(am, __shfl_xor_sync(0xffffffffu, am, o));
        }
        __syncwarp();

        // lag compute: entry e = lane (half A) or cPermB[lane] (half B)
        int e  = (half == 0) ? lane : cPermB[lane];
        int gE = cG[e];
        float out[16];
        ac16v2(sA, sB, cTA[e]*16, 32 + 16*gE, cTB[e]*16, out);

        // intra-group sums via shuffles (members at lane+1, lane+2)
        int cnt = cLeadCnt[lane];
#pragma unroll
        for (int j = 0; j < 16; j++) {
            float v1 = __shfl_down_sync(0xffffffffu, out[j], 1);
            float v2 = __shfl_down_sync(0xffffffffu, out[j], 2);
            if (cnt >= 2) out[j] += v1;
            if (cnt >= 3) out[j] += v2;
        }
        // local argmax on lead lanes (slot = 16*g + j; lag = 32 + slot)
        float bv = -FLT_MAX; int bi = 0x7fffffff;
        if (cnt > 0) {
            int base = 16*gE;
#pragma unroll
            for (int j = 0; j < 16; j++)
                if (out[j] > bv) { bv = out[j]; bi = base + j; }
        }
        // warp argmax, first-max tie rule (smaller slot wins ties)
        for (int o = 16; o; o >>= 1) {
            float ov = __shfl_down_sync(0xffffffffu, bv, o);
            int   oi = __shfl_down_sync(0xffffffffu, bi, o);
            if (ov > bv || (ov == bv && oi < bi)) { bv = ov; bi = oi; }
        }
        if (lane == 0) {
            int idx = b*NF + f;
            float rms = sqrtf(ss / (float)FRAME);
            float zcr = zc / (2.f * (float)FRAME);
            int peak = bi + 32;
            float f0 = 16000.f / (float)peak;
            float valid = (bv > 0.3f*ss && f0 > 50.f && f0 < 500.f) ? 1.f : 0.f;
            g_rms[idx] = rms; g_zcr[idx] = zcr; g_amp[idx] = am;
            g_f0[idx] = f0;  g_val[idx] = valid;
        }
        __syncwarp();   // buffer reuse across halves
    }
}

// ------------------------- K2: per-signal frame aggregation -----------------
__device__ __forceinline__ float blockReduce512(float v, float* sred, int tid)
{
    sred[tid] = v; __syncthreads();
    for (int st = 256; st > 0; st >>= 1) {
        if (tid < st) sred[tid] += sred[tid + st];
        __syncthreads();
    }
    float r = sred[0]; __syncthreads();
    return r;
}

__global__ __launch_bounds__(512) void k_sigstats()
{
    int b = blockIdx.x, tid = threadIdx.x;
    __shared__ float sred[512];
    __shared__ float samp[1024];
    __shared__ int   cCA[1024], cCB[1024];
    __shared__ float comp[1024];

    float sr=0.f, sz=0.f, sf0=0.f, fc=0.f, vo=0.f;
    for (int i = tid; i < NF; i += 512) {
        float r = g_rms[b*NF+i], z = g_zcr[b*NF+i];
        float f = g_f0[b*NF+i],  v = g_val[b*NF+i];
        sr += r; sz += z; sf0 += f*v; fc += v;
        vo += (r > 0.01f && z < 0.3f) ? 1.f : 0.f;
    }
    float SR = blockReduce512(sr, sred, tid);
    float SZ = blockReduce512(sz, sred, tid);
    float SF = blockReduce512(sf0, sred, tid);
    float FC = blockReduce512(fc, sred, tid);
    float VO = blockReduce512(vo, sred, tid);

    float e_mean = SR / (float)NF;
    float z_mean = SZ / (float)NF;
    float f0_mean = SF / fmaxf(FC, 1.f);

    float dr=0.f, dz=0.f, df=0.f;
    for (int i = tid; i < NF; i += 512) {
        float r = g_rms[b*NF+i], z = g_zcr[b*NF+i];
        float f = g_f0[b*NF+i],  v = g_val[b*NF+i];
        float a1 = r - e_mean, a2 = z - z_mean, a3 = f - f0_mean;
        dr += a1*a1; dz += a2*a2; df += a3*a3*v;
    }
    float DR = blockReduce512(dr, sred, tid);
    float DZ = blockReduce512(dz, sred, tid);
    float DF = blockReduce512(df, sred, tid);

    float e_std  = sqrtf(DR / (float)NF);
    float z_std  = sqrtf(DZ / (float)NF);
    float f0_std = (FC > 0.f) ? sqrtf(DF / fmaxf(FC, 1.f)) : 0.f;
    float f0_m   = (FC > 0.f) ? f0_mean : 0.f;

    for (int i = tid; i < 1024; i += 512) samp[i] = (i < NF) ? g_amp[b*NF+i] : 0.f;
    __syncthreads();
    for (int i = tid; i < 1024; i += 512) cCA[i] = (samp[i] > 0.01f) ? 1 : 0;
    __syncthreads();
    int* src = cCA; int* dst = cCB;
    for (int d = 1; d < 1024; d <<= 1) {
        for (int i = tid; i < 1024; i += 512) dst[i] = src[i] + ((i >= d) ? src[i-d] : 0);
        __syncthreads();
        int* t_ = src; src = dst; dst = t_;
    }
    int ka = src[NF-1];
    for (int i = tid; i < 1024; i += 512)
        if (i < NF && samp[i] > 0.01f) comp[src[i]-1] = samp[i];
    __syncthreads();
    float sd=0.f, sa=0.f;
    for (int r = tid; r < ka; r += 512) {
        sa += comp[r];
        if (r + 1 < ka) sd += fabsf(comp[r+1] - comp[r]);
    }
    float SA = blockReduce512(sa, sred, tid);
    float SD = blockReduce512(sd, sred, tid);

    if (tid == 0) {
        float mean_amp = SA / fmaxf((float)ka, 1.f);
        float mean_ad  = SD / fmaxf((float)(ka-1), 1.f);
        float shim = 0.f;
        if (ka >= 2 && mean_amp > 0.f)
            shim = fminf(fmaxf(mean_ad / fmaxf(mean_amp, 1e-12f), 0.f), 1.f);
        g_sig[b][0]=e_mean; g_sig[b][1]=e_std; g_sig[b][2]=z_mean; g_sig[b][3]=z_std;
        g_sig[b][4]=f0_m;   g_sig[b][5]=f0_std;
        g_sig[b][6]=VO/(float)NF; g_sig[b][7]=shim;
    }
}

// ------------------------- K3: jitter (crossings, 3-phase) ------------------
__global__ __launch_bounds__(1024) void k_jitter(const float* __restrict__ audio)
{
    int b = blockIdx.x, tid = threadIdx.x;
    int warp = tid >> 5, lane = tid & 31;
    __shared__ float sred[1024];
    __shared__ int warpsum[32];
    __shared__ int sK;
    __shared__ float sthr;
    const float* a = audio + (size_t)b*NSAMP;

    float am = 0.f;
    for (int i = tid; i < NSAMP; i += 1024) am = fmaxf(am, fabsf(a[i]));
    for (int o = 16; o; o >>= 1) am = fmaxf(am, __shfl_xor_sync(0xffffffffu, am, o));
    if (lane == 0) sred[warp] = am;
    __syncthreads();
    if (warp == 0) {
        float v = sred[lane];
        for (int o = 16; o; o >>= 1) v = fmaxf(v, __shfl_xor_sync(0xffffffffu, v, o));
        if (lane == 0) sthr = 0.3f * v;
    }
    __syncthreads();
    float thr = sthr;

    const int TOTC = NSAMP - 1;
    int lo = 1 + (int)(((long long)tid * TOTC) >> 10);
    int hi = 1 + (int)(((long long)(tid+1) * TOTC) >> 10);

    int cnt = 0;
    {
        float prev = a[lo-1];
        for (int i = lo; i < hi; i++) {
            float cur = a[i];
            cnt += (prev < thr && cur >= thr) ? 1 : 0;
            prev = cur;
        }
    }
    int inc = cnt;
    for (int o = 1; o < 32; o <<= 1) {
        int n = __shfl_up_sync(0xffffffffu, inc, o);
        if (lane >= o) inc += n;
    }
    if (lane == 31) warpsum[warp] = inc;
    __syncthreads();
    if (warp == 0) {
        int iv = warpsum[lane];
        for (int o = 1; o < 32; o <<= 1) {
            int n = __shfl_up_sync(0xffffffffu, iv, o);
            if (lane >= o) iv += n;
        }
        warpsum[lane] = iv;
        if (lane == 31) sK = iv;
    }
    __syncthreads();
    int base = (warp > 0) ? warpsum[warp-1] : 0;
    int wr = base + inc - cnt;
    {
        float prev = a[lo-1];
        for (int i = lo; i < hi; i++) {
            float cur = a[i];
            if (prev < thr && cur >= thr) g_pos[b][wr++] = i;
            prev = cur;
        }
    }
    __syncthreads();
    int k = sK;

    float sd = 0.f;
    for (int j = tid; j + 2 < k; j += 1024) {
        int p0 = g_pos[b][j], p1 = g_pos[b][j+1], p2 = g_pos[b][j+2];
        sd += fabsf((float)(p2 - 2*p1 + p0));
    }
    sred[tid] = sd; __syncthreads();
    for (int st = 512; st > 0; st >>= 1) {
        if (tid < st) sred[tid] += sred[tid+st];
        __syncthreads();
    }
    if (tid == 0) {
        float nper = (float)(k - 1);
        float mp = 0.f;
        if (k >= 2) mp = (float)(g_pos[b][k-1] - g_pos[b][0]) / fmaxf(nper, 1.f);
        float mpd = sred[0] / fmaxf(nper - 1.f, 1.f);
        g_sig[b][8] = nper; g_sig[b][9] = mp; g_sig[b][10] = mpd;
    }
}

// ------------------------- K4: HNR autocorr partials (scalar, union smem) ---
__global__ __launch_bounds__(320) void k_hnr(const float* __restrict__ audio)
{
    int c = blockIdx.x, b = blockIdx.y;
    int tid = threadIdx.x;
    __shared__ float u[5136];         // union: samples PIDX(4223)=4750 | part 16*321
    const float* a = audio + (size_t)b*NSAMP;
    int base = c*HCLEN;
    for (int i = tid; i < 4224; i += 320) {
        int gi = base + i;
        u[PIDX(i)] = (gi < NSAMP) ? a[gi] : 0.f;
    }
    __syncthreads();
    float out[16];
    {
        int g = tid >> 5, sg = tid & 31;
        int L0 = 48 + g*16;
        int t0 = ((sg*250) >> 5) * 16;
        int t1 = (((sg+1)*250) >> 5) * 16;
        ac16s(u, t0, L0, t1, out);
    }
    __syncthreads();   // all reads of samples done; reuse u as part[]
#pragma unroll
    for (int j = 0; j < 16; j++) u[j*321 + tid] = out[j];
    __syncthreads();
    if (tid < 160) {
        int g2 = tid >> 4, j2 = tid & 15;
        int lag = 48 + g2*16 + j2;
        if (lag >= 50 && lag <= 199) {
            float v = 0.f;
#pragma unroll
            for (int q = 0; q < 32; q++) v += u[j2*321 + g2*32 + q];
            g_hnrp[((size_t)b*HCHUNK + c)*HLAG + (lag - 50)] = v;
        }
    }
}

// ------------------------- K5: HNR finalize (sort + percentile) -------------
__global__ __launch_bounds__(256) void k_hnrfin()
{
    int b = blockIdx.x, tid = threadIdx.x;
    __shared__ float v[256];
    float x = FLT_MAX;
    if (tid < 150) {
        float sacc = 0.f;
        for (int c = 0; c < HCHUNK; c++) sacc += g_hnrp[((size_t)b*HCHUNK + c)*HLAG + tid];
        x = sacc;
    }
    v[tid] = x; __syncthreads();
    for (int k = 2; k <= 256; k <<= 1) {
        for (int j = k >> 1; j > 0; j >>= 1) {
            int ixj = tid ^ j;
            if (ixj > tid) {
                bool up = ((tid & k) == 0);
                float a0 = v[tid], a1 = v[ixj];
                if ((a0 > a1) == up) { v[tid] = a1; v[ixj] = a0; }
            }
            __syncthreads();
        }
    }
    if (tid == 0) {
        float nfl = v[14] + 0.9f*(v[15] - v[14]);  // percentile 10, linear interp
        float sp  = v[149];                          // max of 150 values
        float h = 0.f;
        if (nfl > 0.f) h = fminf(fmaxf(sp / fmaxf(nfl, 1e-30f) / 100.f, 0.f), 1.f);
        g_sig[b][11] = h;
    }
}

// ------------------------- K6: finalize metrics + projection ----------------
__global__ __launch_bounds__(128) void k_final(
    const float* __restrict__ W1, const float* __restrict__ b1,
    const float* __restrict__ gamma, const float* __restrict__ beta,
    const float* __restrict__ W2, const float* __restrict__ b2,
    float* __restrict__ out, int out_size, int B)
{
    int b = blockIdx.x, tid = threadIdx.x;
    __shared__ float feats[10], met[10], hbuf[64], h2[64];
    if (tid == 0) {
        float e_mean=g_sig[b][0], e_std=g_sig[b][1], z_mean=g_sig[b][2], z_std=g_sig[b][3];
        float f0m=g_sig[b][4], f0s=g_sig[b][5], voic=g_sig[b][6], shim=g_sig[b][7];
        float nper=g_sig[b][8], mp=g_sig[b][9], mpd=g_sig[b][10], hnr=g_sig[b][11];
        float jit = 0.f;
        if (nper >= 2.f && mp > 0.f) jit = fminf(fmaxf(mpd / fmaxf(mp, 1e-12f), 0.f), 1.f);
        if (f0m < 50.f || f0m > 500.f) jit = 0.f;
        met[0]=f0m; met[1]=f0s; met[2]=e_mean; met[3]=e_std; met[4]=z_mean; met[5]=z_std;
        met[6]=jit; met[7]=shim; met[8]=hnr; met[9]=voic;
        feats[0]=f0m/500.f; feats[1]=f0s/100.f; feats[2]=e_mean; feats[3]=e_std;
        feats[4]=z_mean; feats[5]=z_std; feats[6]=jit; feats[7]=shim; feats[8]=hnr; feats[9]=voic;
    }
    __syncthreads();
    if (tid < 64) {
        float h = b1[tid];
#pragma unroll
        for (int i = 0; i < 10; i++) h += feats[i] * W1[tid*10 + i];
        hbuf[tid] = h;
    }
    __syncthreads();
    if (tid < 64) {
        float mu = 0.f;
        for (int j = 0; j < 64; j++) mu += hbuf[j];
        mu *= (1.f/64.f);
        float var = 0.f;
        for (int j = 0; j < 64; j++) { float d = hbuf[j] - mu; var += d*d; }
        var *= (1.f/64.f);
        float hn = (hbuf[tid] - mu) / sqrtf(var + 1e-5f) * gamma[tid] + beta[tid];
        h2[tid] = fmaxf(hn, 0.f);
    }
    __syncthreads();
    float o = b2[tid];
#pragma unroll 8
    for (int j = 0; j < 64; j++) o += h2[j] * W2[tid*64 + j];

    if (out_size >= B*138) {
        out[b*128 + tid] = o;
        if (tid < 10) out[B*128 + b*10 + tid] = met[tid];
    } else if (out_size >= B*128) {
        out[b*128 + tid] = o;
    } else {
        if (tid < 10) out[b*10 + tid] = met[tid];
    }
}

// ------------------------- launch -------------------------------------------
extern "C" void kernel_launch(void* const* d_in, const int* in_sizes, int n_in,
                              void* d_out, int out_size)
{
    const float* audio = (const float*)d_in[0];
    const float* W1    = (const float*)d_in[1];
    const float* b1    = (const float*)d_in[2];
    const float* gamma = (const float*)d_in[3];
    const float* beta  = (const float*)d_in[4];
    const float* W2    = (const float*)d_in[5];
    const float* b2    = (const float*)d_in[6];
    int B = in_sizes[0] / NSAMP;
    if (B > MAXB) B = MAXB;

    // order chosen so ncu (-s 5 -c 1) lands on k_frames
    k_jitter<<<B, 1024>>>(audio);
    dim3 g4(HCHUNK, B);
    k_hnr<<<g4, 320>>>(audio);
    k_hnrfin<<<B, 256>>>();
    dim3 g1((NF + 15) / 16, B);
    k_frames<<<g1, 256>>>(audio);
    k_sigstats<<<B, 512>>>();
    k_final<<<B, 128>>>(W1, b1, gamma, beta, W2, b2, (float*)d_out, out_size, B);
}

// round 10
// speedup vs baseline: 1.0517x; 1.0517x over previous
#include <cuda_runtime.h>
#include <math.h>
#include <float.h>

#define NSAMP  160000
#define NF     998
#define FRAME  400
#define HOP    160
#define MAXB   128
#define NLAG   288      // lags 32..319
#define HLAG   152      // hnr lag slots (150 used: lags 50..199)
#define HCHUNK 40
#define HCLEN  4000

// padded smem index: insert one float after every 8
#define PIDX(i) ((i) + ((i) >> 3))

// ------------------------- device scratch (static, no allocs) ---------------
__device__ float g_rms[MAXB*NF];
__device__ float g_zcr[MAXB*NF];
__device__ float g_amp[MAXB*NF];
__device__ float g_f0 [MAXB*NF];
__device__ float g_val[MAXB*NF];
__device__ int   g_pos[MAXB][NSAMP];
__device__ float g_sig[MAXB][12];
__device__ float g_hnrp[(size_t)MAXB*HCHUNK*HLAG];

// ---- k_frames entry tables (18 groups of 16 lags, 261 16-sample tiles) -----
__constant__ int cG [32] = {0,0,0,1,1,2,2,3,3,4,4,5,5,6,6,7,7,8,8,9,9,10,10,11,11,12,12,13,14,15,16,17};
__constant__ int cTA[32] = {0,8,16,0,11,0,11,0,10,0,10,0,9,0,9,0,8,0,8,0,7,0,7,0,6,0,6,0,0,0,0,0};
__constant__ int cTB[32] = {8,16,23,11,22,11,21,10,20,10,19,9,18,9,17,8,16,8,15,7,14,7,13,6,12,6,11,10,9,8,7,6};
// half-B lane->entry map: groups stay lane-contiguous, per-lane A+B tiles <= 17
__constant__ int cPermB[32] = {0,1,2,25,26,23,24,21,22,19,20,17,18,15,16,13,14,11,12,9,10,7,8,5,6,3,4,31,30,29,28,27};
// group-lead lane -> member count (same for both halves); 0 = not a lead
__constant__ int cLeadCnt[32] = {3,0,0,2,0,2,0,2,0,2,0,2,0,2,0,2,0,2,0,2,0,2,0,2,0,2,0,1,1,1,1,1};

// 16-lag scalar sliding-window autocorr. t0, L0 multiples of 16.
// buffer zero-padded beyond data so overrun products vanish.
__device__ __forceinline__ void ac16s(const float* __restrict__ sf,
                                      int t0, int L0, int t1, float* out)
{
    float wreg[16], acc[16];
    int pb0 = PIDX(t0 + L0);
#pragma unroll
    for (int j = 0; j < 16; j++) { wreg[j] = sf[pb0 + j + (j>>3)]; acc[j] = 0.f; }
    #pragma unroll 1
    for (int tb = t0; tb < t1; tb += 16) {
        int pB = PIDX(tb);
        int pW = PIDX(tb + L0 + 16);
#pragma unroll
        for (int u = 0; u < 16; u++) {
            float bb = sf[pB + u + (u>>3)];
#pragma unroll
            for (int j = 0; j < 16; j++) acc[j] += bb * wreg[(u + j) & 15];
            wreg[u] = sf[pW + u + (u>>3)];
        }
    }
#pragma unroll
    for (int j = 0; j < 16; j++) out[j] = acc[j];
}

// ------------------------- K1: per-frame stats + autocorr -------------------
// One warp per frame, 2 frames per warp. Group partials summed via shuffles
// (groups lane-contiguous in both halves) -> no part[] smem at all.
__global__ __launch_bounds__(256) void k_frames(const float* __restrict__ audio)
{
    __shared__ float sbuf[16*472];    // per-(warp,half) zero-padded frame
    const int tid = threadIdx.x, w = tid >> 5, lane = tid & 31;
    const int b = blockIdx.y;
    const int fbase = blockIdx.x*16 + 2*w;

    #pragma unroll 1
    for (int half = 0; half < 2; half++) {
        int f = fbase + half;
        if (f >= NF) break;           // warp-uniform
        float* sfW = sbuf + (w*2 + half)*472;
        const float* a = audio + (size_t)b*NSAMP + (size_t)f*HOP;

        // load + stats (rms/zcr/amp fused; sign via shuffles)
        float ss = 0.f, am = 0.f, zc = 0.f, prevs31 = 0.f;
        #pragma unroll 1
        for (int k = 0; k < 14; k++) {
            int i = lane + 32*k;
            float x = (i < FRAME) ? a[i] : 0.f;
            if (i < 420) sfW[PIDX(i)] = x;
            ss += x*x;
            am = fmaxf(am, fabsf(x));
            float sg = (float)((x > 0.f) - (x < 0.f));
            float ps = __shfl_up_sync(0xffffffffu, sg, 1);
            if (lane == 0) ps = prevs31;
            if (i >= 1 && i < FRAME) zc += fabsf(sg - ps);
            prevs31 = __shfl_sync(0xffffffffu, sg, 31);
        }
        for (int o = 16; o; o >>= 1) {
            ss += __shfl_xor_sync(0xffffffffu, ss, o);
            zc += __shfl_xor_sync(0xffffffffu, zc, o);
            am  = fmaxf(am, __shfl_xor_sync(0xffffffffu, am, o));
        }
        __syncwarp();

        // lag compute: entry e = lane (half A) or cPermB[lane] (half B)
        int e  = (half == 0) ? lane : cPermB[lane];
        int gE = cG[e];
        float out[16];
        ac16s(sfW, cTA[e]*16, 32 + 16*gE, cTB[e]*16, out);

        // intra-group sums via shuffles (members at lane+1, lane+2)
        int cnt = cLeadCnt[lane];
#pragma unroll
        for (int j = 0; j < 16; j++) {
            float v1 = __shfl_down_sync(0xffffffffu, out[j], 1);
            float v2 = __shfl_down_sync(0xffffffffu, out[j], 2);
            if (cnt >= 2) out[j] += v1;
            if (cnt >= 3) out[j] += v2;
        }
        // local argmax on lead lanes (slot = 16*g + j; lag = 32 + slot)
        float bv = -FLT_MAX; int bi = 0x7fffffff;
        if (cnt > 0) {
            int base = 16*gE;
#pragma unroll
            for (int j = 0; j < 16; j++)
                if (out[j] > bv) { bv = out[j]; bi = base + j; }
        }
        // warp argmax, first-max tie rule (smaller slot wins ties)
        for (int o = 16; o; o >>= 1) {
            float ov = __shfl_down_sync(0xffffffffu, bv, o);
            int   oi = __shfl_down_sync(0xffffffffu, bi, o);
            if (ov > bv || (ov == bv && oi < bi)) { bv = ov; bi = oi; }
        }
        if (lane == 0) {
            int idx = b*NF + f;
            float rms = sqrtf(ss / (float)FRAME);
            float zcr = zc / (2.f * (float)FRAME);
            int peak = bi + 32;
            float f0 = 16000.f / (float)peak;
            float valid = (bv > 0.3f*ss && f0 > 50.f && f0 < 500.f) ? 1.f : 0.f;
            g_rms[idx] = rms; g_zcr[idx] = zcr; g_amp[idx] = am;
            g_f0[idx] = f0;  g_val[idx] = valid;
        }
        __syncwarp();   // sbuf half reuse safety
    }
}

// ------------------------- K2: per-signal frame aggregation -----------------
__device__ __forceinline__ float blockReduce512(float v, float* sred, int tid)
{
    sred[tid] = v; __syncthreads();
    for (int st = 256; st > 0; st >>= 1) {
        if (tid < st) sred[tid] += sred[tid + st];
        __syncthreads();
    }
    float r = sred[0]; __syncthreads();
    return r;
}

__global__ __launch_bounds__(512) void k_sigstats()
{
    int b = blockIdx.x, tid = threadIdx.x;
    __shared__ float sred[512];
    __shared__ float samp[1024];
    __shared__ int   cCA[1024], cCB[1024];
    __shared__ float comp[1024];

    float sr=0.f, sz=0.f, sf0=0.f, fc=0.f, vo=0.f;
    for (int i = tid; i < NF; i += 512) {
        float r = g_rms[b*NF+i], z = g_zcr[b*NF+i];
        float f = g_f0[b*NF+i],  v = g_val[b*NF+i];
        sr += r; sz += z; sf0 += f*v; fc += v;
        vo += (r > 0.01f && z < 0.3f) ? 1.f : 0.f;
    }
    float SR = blockReduce512(sr, sred, tid);
    float SZ = blockReduce512(sz, sred, tid);
    float SF = blockReduce512(sf0, sred, tid);
    float FC = blockReduce512(fc, sred, tid);
    float VO = blockReduce512(vo, sred, tid);

    float e_mean = SR / (float)NF;
    float z_mean = SZ / (float)NF;
    float f0_mean = SF / fmaxf(FC, 1.f);

    float dr=0.f, dz=0.f, df=0.f;
    for (int i = tid; i < NF; i += 512) {
        float r = g_rms[b*NF+i], z = g_zcr[b*NF+i];
        float f = g_f0[b*NF+i],  v = g_val[b*NF+i];
        float a1 = r - e_mean, a2 = z - z_mean, a3 = f - f0_mean;
        dr += a1*a1; dz += a2*a2; df += a3*a3*v;
    }
    float DR = blockReduce512(dr, sred, tid);
    float DZ = blockReduce512(dz, sred, tid);
    float DF = blockReduce512(df, sred, tid);

    float e_std  = sqrtf(DR / (float)NF);
    float z_std  = sqrtf(DZ / (float)NF);
    float f0_std = (FC > 0.f) ? sqrtf(DF / fmaxf(FC, 1.f)) : 0.f;
    float f0_m   = (FC > 0.f) ? f0_mean : 0.f;

    for (int i = tid; i < 1024; i += 512) samp[i] = (i < NF) ? g_amp[b*NF+i] : 0.f;
    __syncthreads();
    for (int i = tid; i < 1024; i += 512) cCA[i] = (samp[i] > 0.01f) ? 1 : 0;
    __syncthreads();
    int* src = cCA; int* dst = cCB;
    for (int d = 1; d < 1024; d <<= 1) {
        for (int i = tid; i < 1024; i += 512) dst[i] = src[i] + ((i >= d) ? src[i-d] : 0);
        __syncthreads();
        int* t_ = src; src = dst; dst = t_;
    }
    int ka = src[NF-1];
    for (int i = tid; i < 1024; i += 512)
        if (i < NF && samp[i] > 0.01f) comp[src[i]-1] = samp[i];
    __syncthreads();
    float sd=0.f, sa=0.f;
    for (int r = tid; r < ka; r += 512) {
        sa += comp[r];
        if (r + 1 < ka) sd += fabsf(comp[r+1] - comp[r]);
    }
    float SA = blockReduce512(sa, sred, tid);
    float SD = blockReduce512(sd, sred, tid);

    if (tid == 0) {
        float mean_amp = SA / fmaxf((float)ka, 1.f);
        float mean_ad  = SD / fmaxf((float)(ka-1), 1.f);
        float shim = 0.f;
        if (ka >= 2 && mean_amp > 0.f)
            shim = fminf(fmaxf(mean_ad / fmaxf(mean_amp, 1e-12f), 0.f), 1.f);
        g_sig[b][0]=e_mean; g_sig[b][1]=e_std; g_sig[b][2]=z_mean; g_sig[b][3]=z_std;
        g_sig[b][4]=f0_m;   g_sig[b][5]=f0_std;
        g_sig[b][6]=VO/(float)NF; g_sig[b][7]=shim;
    }
}

// ------------------------- K3: jitter (crossings, 3-phase) ------------------
__global__ __launch_bounds__(1024) void k_jitter(const float* __restrict__ audio)
{
    int b = blockIdx.x, tid = threadIdx.x;
    int warp = tid >> 5, lane = tid & 31;
    __shared__ float sred[1024];
    __shared__ int warpsum[32];
    __shared__ int sK;
    __shared__ float sthr;
    const float* a = audio + (size_t)b*NSAMP;

    float am = 0.f;
    for (int i = tid; i < NSAMP; i += 1024) am = fmaxf(am, fabsf(a[i]));
    for (int o = 16; o; o >>= 1) am = fmaxf(am, __shfl_xor_sync(0xffffffffu, am, o));
    if (lane == 0) sred[warp] = am;
    __syncthreads();
    if (warp == 0) {
        float v = sred[lane];
        for (int o = 16; o; o >>= 1) v = fmaxf(v, __shfl_xor_sync(0xffffffffu, v, o));
        if (lane == 0) sthr = 0.3f * v;
    }
    __syncthreads();
    float thr = sthr;

    const int TOTC = NSAMP - 1;
    int lo = 1 + (int)(((long long)tid * TOTC) >> 10);
    int hi = 1 + (int)(((long long)(tid+1) * TOTC) >> 10);

    int cnt = 0;
    {
        float prev = a[lo-1];
        for (int i = lo; i < hi; i++) {
            float cur = a[i];
            cnt += (prev < thr && cur >= thr) ? 1 : 0;
            prev = cur;
        }
    }
    int inc = cnt;
    for (int o = 1; o < 32; o <<= 1) {
        int n = __shfl_up_sync(0xffffffffu, inc, o);
        if (lane >= o) inc += n;
    }
    if (lane == 31) warpsum[warp] = inc;
    __syncthreads();
    if (warp == 0) {
        int iv = warpsum[lane];
        for (int o = 1; o < 32; o <<= 1) {
            int n = __shfl_up_sync(0xffffffffu, iv, o);
            if (lane >= o) iv += n;
        }
        warpsum[lane] = iv;
        if (lane == 31) sK = iv;
    }
    __syncthreads();
    int base = (warp > 0) ? warpsum[warp-1] : 0;
    int wr = base + inc - cnt;
    {
        float prev = a[lo-1];
        for (int i = lo; i < hi; i++) {
            float cur = a[i];
            if (prev < thr && cur >= thr) g_pos[b][wr++] = i;
            prev = cur;
        }
    }
    __syncthreads();
    int k = sK;

    float sd = 0.f;
    for (int j = tid; j + 2 < k; j += 1024) {
        int p0 = g_pos[b][j], p1 = g_pos[b][j+1], p2 = g_pos[b][j+2];
        sd += fabsf((float)(p2 - 2*p1 + p0));
    }
    sred[tid] = sd; __syncthreads();
    for (int st = 512; st > 0; st >>= 1) {
        if (tid < st) sred[tid] += sred[tid+st];
        __syncthreads();
    }
    if (tid == 0) {
        float nper = (float)(k - 1);
        float mp = 0.f;
        if (k >= 2) mp = (float)(g_pos[b][k-1] - g_pos[b][0]) / fmaxf(nper, 1.f);
        float mpd = sred[0] / fmaxf(nper - 1.f, 1.f);
        g_sig[b][8] = nper; g_sig[b][9] = mp; g_sig[b][10] = mpd;
    }
}

// ------------------------- K4: HNR autocorr partials (scalar, union smem) ---
__global__ __launch_bounds__(320) void k_hnr(const float* __restrict__ audio)
{
    int c = blockIdx.x, b = blockIdx.y;
    int tid = threadIdx.x;
    __shared__ float u[5136];         // union: samples PIDX(4223)=4750 | part 16*321
    const float* a = audio + (size_t)b*NSAMP;
    int base = c*HCLEN;
    for (int i = tid; i < 4224; i += 320) {
        int gi = base + i;
        u[PIDX(i)] = (gi < NSAMP) ? a[gi] : 0.f;
    }
    __syncthreads();
    float out[16];
    {
        int g = tid >> 5, sg = tid & 31;
        int L0 = 48 + g*16;
        int t0 = ((sg*250) >> 5) * 16;
        int t1 = (((sg+1)*250) >> 5) * 16;
        ac16s(u, t0, L0, t1, out);
    }
    __syncthreads();   // all reads of samples done; reuse u as part[]
#pragma unroll
    for (int j = 0; j < 16; j++) u[j*321 + tid] = out[j];
    __syncthreads();
    if (tid < 160) {
        int g2 = tid >> 4, j2 = tid & 15;
        int lag = 48 + g2*16 + j2;
        if (lag >= 50 && lag <= 199) {
            float v = 0.f;
#pragma unroll
            for (int q = 0; q < 32; q++) v += u[j2*321 + g2*32 + q];
            g_hnrp[((size_t)b*HCHUNK + c)*HLAG + (lag - 50)] = v;
        }
    }
}

// ------------------------- K5: HNR finalize (sort + percentile) -------------
__global__ __launch_bounds__(256) void k_hnrfin()
{
    int b = blockIdx.x, tid = threadIdx.x;
    __shared__ float v[256];
    float x = FLT_MAX;
    if (tid < 150) {
        float sacc = 0.f;
        for (int c = 0; c < HCHUNK; c++) sacc += g_hnrp[((size_t)b*HCHUNK + c)*HLAG + tid];
        x = sacc;
    }
    v[tid] = x; __syncthreads();
    for (int k = 2; k <= 256; k <<= 1) {
        for (int j = k >> 1; j > 0; j >>= 1) {
            int ixj = tid ^ j;
            if (ixj > tid) {
                bool up = ((tid & k) == 0);
                float a0 = v[tid], a1 = v[ixj];
                if ((a0 > a1) == up) { v[tid] = a1; v[ixj] = a0; }
            }
            __syncthreads();
        }
    }
    if (tid == 0) {
        float nfl = v[14] + 0.9f*(v[15] - v[14]);  // percentile 10, linear interp
        float sp  = v[149];                          // max of 150 values
        float h = 0.f;
        if (nfl > 0.f) h = fminf(fmaxf(sp / fmaxf(nfl, 1e-30f) / 100.f, 0.f), 1.f);
        g_sig[b][11] = h;
    }
}

// ------------------------- K6: finalize metrics + projection ----------------
__global__ __launch_bounds__(128) void k_final(
    const float* __restrict__ W1, const float* __restrict__ b1,
    const float* __restrict__ gamma, const float* __restrict__ beta,
    const float* __restrict__ W2, const float* __restrict__ b2,
    float* __restrict__ out, int out_size, int B)
{
    int b = blockIdx.x, tid = threadIdx.x;
    __shared__ float feats[10], met[10], hbuf[64], h2[64];
    if (tid == 0) {
        float e_mean=g_sig[b][0], e_std=g_sig[b][1], z_mean=g_sig[b][2], z_std=g_sig[b][3];
        float f0m=g_sig[b][4], f0s=g_sig[b][5], voic=g_sig[b][6], shim=g_sig[b][7];
        float nper=g_sig[b][8], mp=g_sig[b][9], mpd=g_sig[b][10], hnr=g_sig[b][11];
        float jit = 0.f;
        if (nper >= 2.f && mp > 0.f) jit = fminf(fmaxf(mpd / fmaxf(mp, 1e-12f), 0.f), 1.f);
        if (f0m < 50.f || f0m > 500.f) jit = 0.f;
        met[0]=f0m; met[1]=f0s; met[2]=e_mean; met[3]=e_std; met[4]=z_mean; met[5]=z_std;
        met[6]=jit; met[7]=shim; met[8]=hnr; met[9]=voic;
        feats[0]=f0m/500.f; feats[1]=f0s/100.f; feats[2]=e_mean; feats[3]=e_std;
        feats[4]=z_mean; feats[5]=z_std; feats[6]=jit; feats[7]=shim; feats[8]=hnr; feats[9]=voic;
    }
    __syncthreads();
    if (tid < 64) {
        float h = b1[tid];
#pragma unroll
        for (int i = 0; i < 10; i++) h += feats[i] * W1[tid*10 + i];
        hbuf[tid] = h;
    }
    __syncthreads();
    if (tid < 64) {
        float mu = 0.f;
        for (int j = 0; j < 64; j++) mu += hbuf[j];
        mu *= (1.f/64.f);
        float var = 0.f;
        for (int j = 0; j < 64; j++) { float d = hbuf[j] - mu; var += d*d; }
        var *= (1.f/64.f);
        float hn = (hbuf[tid] - mu) / sqrtf(var + 1e-5f) * gamma[tid] + beta[tid];
        h2[tid] = fmaxf(hn, 0.f);
    }
    __syncthreads();
    float o = b2[tid];
#pragma unroll 8
    for (int j = 0; j < 64; j++) o += h2[j] * W2[tid*64 + j];

    if (out_size >= B*138) {
        out[b*128 + tid] = o;
        if (tid < 10) out[B*128 + b*10 + tid] = met[tid];
    } else if (out_size >= B*128) {
        out[b*128 + tid] = o;
    } else {
        if (tid < 10) out[b*10 + tid] = met[tid];
    }
}

// ------------------------- launch (multi-stream fork-join) ------------------
static cudaStream_t g_s1, g_s2;
static cudaEvent_t  g_e0, g_e1, g_e2;
static bool g_streams_ready = false;

extern "C" void kernel_launch(void* const* d_in, const int* in_sizes, int n_in,
                              void* d_out, int out_size)
{
    const float* audio = (const float*)d_in[0];
    const float* W1    = (const float*)d_in[1];
    const float* b1    = (const float*)d_in[2];
    const float* gamma = (const float*)d_in[3];
    const float* beta  = (const float*)d_in[4];
    const float* W2    = (const float*)d_in[5];
    const float* b2    = (const float*)d_in[6];
    int B = in_sizes[0] / NSAMP;
    if (B > MAXB) B = MAXB;

    // one-time host-side resource setup (first call is the uncaptured
    // correctness run; captured calls perform identical device work)
    if (!g_streams_ready) {
        cudaStreamCreateWithFlags(&g_s1, cudaStreamNonBlocking);
        cudaStreamCreateWithFlags(&g_s2, cudaStreamNonBlocking);
        cudaEventCreateWithFlags(&g_e0, cudaEventDisableTiming);
        cudaEventCreateWithFlags(&g_e1, cudaEventDisableTiming);
        cudaEventCreateWithFlags(&g_e2, cudaEventDisableTiming);
        g_streams_ready = true;
    }

    // fork
    cudaEventRecord(g_e0, 0);
    cudaStreamWaitEvent(g_s1, g_e0, 0);
    cudaStreamWaitEvent(g_s2, g_e0, 0);

    // branch 1: jitter (memory-bound)
    k_jitter<<<B, 1024, 0, g_s1>>>(audio);
    cudaEventRecord(g_e1, g_s1);

    // branch 2: hnr chain (fma-bound)
    dim3 g4(HCHUNK, B);
    k_hnr<<<g4, 320, 0, g_s2>>>(audio);
    k_hnrfin<<<B, 256, 0, g_s2>>>();
    cudaEventRecord(g_e2, g_s2);

    // main branch: frames chain (fma-bound, dominant)
    dim3 g1((NF + 15) / 16, B);
    k_frames<<<g1, 256>>>(audio);
    k_sigstats<<<B, 512>>>();

    // join
    cudaStreamWaitEvent(0, g_e1, 0);
    cudaStreamWaitEvent(0, g_e2, 0);
    k_final<<<B, 128>>>(W1, b1, gamma, beta, W2, b2, (float*)d_out, out_size, B);
}